// round 3
// baseline (speedup 1.0000x reference)
#include <cuda_runtime.h>

// Problem constants
#define BB   8
#define CC   768
#define DD   512
#define HWW  1024
#define LQQ  2048   // LEVELS*HW
#define NHEAD 8
#define NLVL  2
#define NPT   4

// ---------------- scratch (device globals; no runtime allocation) ----------------
__device__ float g_conv1  [(size_t)BB*2*DD*HWW];   // conv1 outputs, (b,lvl,d,hw)
__device__ float g_src    [(size_t)BB*LQQ*DD];
__device__ float g_query  [(size_t)BB*LQQ*DD];
__device__ float g_vproj  [(size_t)BB*LQQ*DD];
__device__ float g_off    [(size_t)BB*LQQ*128];
__device__ float g_aw     [(size_t)BB*LQQ*64];
__device__ float g_msout  [(size_t)BB*LQQ*DD];
__device__ float g_attno  [(size_t)BB*LQQ*DD];
__device__ float g_lnout  [(size_t)BB*LQQ*DD];
__device__ float g_conv2  [(size_t)BB*CC*HWW];
__device__ float g_stats1 [BB*2*32*2];
__device__ float g_stats2 [BB*32*2];

// ---------------- SGEMM NN:  C[b] = A(MxK) * B[b](KxN) + biasM ----------------
// A row-major shared over batch; B,C batched by stride. 128x128x8 tiles, 8x8/thread.
__global__ __launch_bounds__(256) void sgemm_nn(
    const float* __restrict__ A, const float* __restrict__ Bg,
    float* __restrict__ Cg, const float* __restrict__ biasM,
    int M, int N, int K, long strideB, long strideC)
{
    __shared__ float As[8][128];
    __shared__ float Bs[8][128];
    const float* Bp = Bg + (size_t)blockIdx.z * strideB;
    float* Cp       = Cg + (size_t)blockIdx.z * strideC;
    int m0 = blockIdx.y * 128, n0 = blockIdx.x * 128;
    int tid = threadIdx.x;
    int tx = tid & 15, ty = tid >> 4;
    int lm = tid >> 1, lk = (tid & 1) * 4;
    int bk = tid >> 5, bn = (tid & 31) * 4;
    float acc[8][8] = {};
    for (int k0 = 0; k0 < K; k0 += 8) {
        float4 av = *(const float4*)(A + (size_t)(m0 + lm) * K + k0 + lk);
        As[lk+0][lm] = av.x; As[lk+1][lm] = av.y; As[lk+2][lm] = av.z; As[lk+3][lm] = av.w;
        *(float4*)&Bs[bk][bn] = *(const float4*)(Bp + (size_t)(k0 + bk) * N + n0 + bn);
        __syncthreads();
        #pragma unroll
        for (int kk = 0; kk < 8; kk++) {
            float a[8], bb[8];
            *(float4*)(a)    = *(const float4*)&As[kk][ty*8];
            *(float4*)(a+4)  = *(const float4*)&As[kk][ty*8+4];
            *(float4*)(bb)   = *(const float4*)&Bs[kk][tx*8];
            *(float4*)(bb+4) = *(const float4*)&Bs[kk][tx*8+4];
            #pragma unroll
            for (int i = 0; i < 8; i++)
                #pragma unroll
                for (int j = 0; j < 8; j++) acc[i][j] = fmaf(a[i], bb[j], acc[i][j]);
        }
        __syncthreads();
    }
    #pragma unroll
    for (int i = 0; i < 8; i++) {
        int m = m0 + ty*8 + i;
        float bia = biasM[m];
        #pragma unroll
        for (int j = 0; j < 8; j += 4) {
            float4 v;
            v.x = acc[i][j+0] + bia; v.y = acc[i][j+1] + bia;
            v.z = acc[i][j+2] + bia; v.w = acc[i][j+3] + bia;
            *(float4*)(Cp + (size_t)m * N + n0 + tx*8 + j) = v;
        }
    }
}

// ---------------- SGEMM NT:  C = X(MxK) * W(NxK)^T + biasN ----------------
__global__ __launch_bounds__(256) void sgemm_nt(
    const float* __restrict__ X, const float* __restrict__ W,
    float* __restrict__ Cg, const float* __restrict__ biasN,
    int M, int N, int K)
{
    __shared__ float Xs[8][128];
    __shared__ float Ws[8][128];
    int m0 = blockIdx.y * 128, n0 = blockIdx.x * 128;
    int tid = threadIdx.x;
    int tx = tid & 15, ty = tid >> 4;
    int lm = tid >> 1, lk = (tid & 1) * 4;
    float acc[8][8] = {};
    for (int k0 = 0; k0 < K; k0 += 8) {
        float4 xv = *(const float4*)(X + (size_t)(m0 + lm) * K + k0 + lk);
        Xs[lk+0][lm] = xv.x; Xs[lk+1][lm] = xv.y; Xs[lk+2][lm] = xv.z; Xs[lk+3][lm] = xv.w;
        float4 wv4 = make_float4(0.f, 0.f, 0.f, 0.f);
        if (n0 + lm < N)
            wv4 = *(const float4*)(W + (size_t)(n0 + lm) * K + k0 + lk);
        Ws[lk+0][lm] = wv4.x; Ws[lk+1][lm] = wv4.y; Ws[lk+2][lm] = wv4.z; Ws[lk+3][lm] = wv4.w;
        __syncthreads();
        #pragma unroll
        for (int kk = 0; kk < 8; kk++) {
            float a[8], bb[8];
            *(float4*)(a)    = *(const float4*)&Xs[kk][ty*8];
            *(float4*)(a+4)  = *(const float4*)&Xs[kk][ty*8+4];
            *(float4*)(bb)   = *(const float4*)&Ws[kk][tx*8];
            *(float4*)(bb+4) = *(const float4*)&Ws[kk][tx*8+4];
            #pragma unroll
            for (int i = 0; i < 8; i++)
                #pragma unroll
                for (int j = 0; j < 8; j++) acc[i][j] = fmaf(a[i], bb[j], acc[i][j]);
        }
        __syncthreads();
    }
    #pragma unroll
    for (int i = 0; i < 8; i++) {
        int m = m0 + ty*8 + i;
        #pragma unroll
        for (int j = 0; j < 8; j += 4) {
            int n = n0 + tx*8 + j;
            if (n < N) {
                float4 v;
                v.x = acc[i][j+0] + biasN[n+0]; v.y = acc[i][j+1] + biasN[n+1];
                v.z = acc[i][j+2] + biasN[n+2]; v.w = acc[i][j+3] + biasN[n+3];
                *(float4*)(Cg + (size_t)m * N + n) = v;
            }
        }
    }
}

// ---------------- final conv GEMM: C[b,o,hw] = sum_k wc[o,k] * lnout-mapped ----------------
// lnout is (B, 2048, 512); logical B[k,hw] = lnout[b, (k>=512)*1024+hw, k&511]
__global__ __launch_bounds__(256) void sgemm_conv2(
    const float* __restrict__ A, const float* __restrict__ lnout,
    float* __restrict__ Cg, const float* __restrict__ biasM)
{
    const int M = 768, N = 1024, K = 1024;
    __shared__ float As[8][128];
    __shared__ float Bs[8][128];
    int b = blockIdx.z;
    float* Cp = Cg + (size_t)b * M * N;
    int m0 = blockIdx.y * 128, n0 = blockIdx.x * 128;
    int tid = threadIdx.x;
    int tx = tid & 15, ty = tid >> 4;
    int lm = tid >> 1, lk = (tid & 1) * 4;
    float acc[8][8] = {};
    for (int k0 = 0; k0 < K; k0 += 8) {
        float4 av = *(const float4*)(A + (size_t)(m0 + lm) * K + k0 + lk);
        As[lk+0][lm] = av.x; As[lk+1][lm] = av.y; As[lk+2][lm] = av.z; As[lk+3][lm] = av.w;
        int lvl = k0 >> 9;
        const float* bp = lnout + ((size_t)(b*2 + lvl) * 1024 + n0 + lm) * 512 + (k0 & 511) + lk;
        float4 bv = *(const float4*)bp;
        Bs[lk+0][lm] = bv.x; Bs[lk+1][lm] = bv.y; Bs[lk+2][lm] = bv.z; Bs[lk+3][lm] = bv.w;
        __syncthreads();
        #pragma unroll
        for (int kk = 0; kk < 8; kk++) {
            float a[8], bb[8];
            *(float4*)(a)    = *(const float4*)&As[kk][ty*8];
            *(float4*)(a+4)  = *(const float4*)&As[kk][ty*8+4];
            *(float4*)(bb)   = *(const float4*)&Bs[kk][tx*8];
            *(float4*)(bb+4) = *(const float4*)&Bs[kk][tx*8+4];
            #pragma unroll
            for (int i = 0; i < 8; i++)
                #pragma unroll
                for (int j = 0; j < 8; j++) acc[i][j] = fmaf(a[i], bb[j], acc[i][j]);
        }
        __syncthreads();
    }
    #pragma unroll
    for (int i = 0; i < 8; i++) {
        int m = m0 + ty*8 + i;
        float bia = biasM[m];
        #pragma unroll
        for (int j = 0; j < 8; j += 4) {
            float4 v;
            v.x = acc[i][j+0] + bia; v.y = acc[i][j+1] + bia;
            v.z = acc[i][j+2] + bia; v.w = acc[i][j+3] + bia;
            *(float4*)(Cp + (size_t)m * N + n0 + tx*8 + j) = v;
        }
    }
}

// ---------------- GroupNorm stats: contiguous groups ----------------
__global__ void gn_stats(const float* __restrict__ x, float* __restrict__ stats, int groupElems)
{
    int idx = blockIdx.y * gridDim.x + blockIdx.x;
    const float* p = x + (size_t)idx * groupElems;
    float s = 0.f, sq = 0.f;
    for (int i = threadIdx.x; i < groupElems; i += blockDim.x) {
        float v = p[i]; s += v; sq += v * v;
    }
    __shared__ float red[16];
    int t = threadIdx.x;
    for (int o = 16; o > 0; o >>= 1) {
        s  += __shfl_down_sync(0xffffffffu, s,  o);
        sq += __shfl_down_sync(0xffffffffu, sq, o);
    }
    if ((t & 31) == 0) { red[t >> 5] = s; red[8 + (t >> 5)] = sq; }
    __syncthreads();
    if (t < 32) {
        s  = (t < 8) ? red[t]     : 0.f;
        sq = (t < 8) ? red[8 + t] : 0.f;
        for (int o = 4; o > 0; o >>= 1) {
            s  += __shfl_down_sync(0xffffffffu, s,  o);
            sq += __shfl_down_sync(0xffffffffu, sq, o);
        }
        if (t == 0) {
            float inv = 1.f / (float)groupElems;
            float mean = s * inv;
            float var  = sq * inv - mean * mean;
            stats[idx*2]   = mean;
            stats[idx*2+1] = rsqrtf(var + 1e-5f);
        }
    }
}

// ---------------- GN1 normalize + transpose -> src, query ----------------
// grid (32 hw-tiles, 16 d-tiles, B*2), block (32,8)
__global__ void gn1_finish(const float* __restrict__ conv, const float* __restrict__ stats,
    const float* __restrict__ gv, const float* __restrict__ bev,
    const float* __restrict__ gi, const float* __restrict__ bei,
    const float* __restrict__ le,
    float* __restrict__ src, float* __restrict__ query)
{
    __shared__ float tile[32][33];
    int be = blockIdx.z;
    int b = be >> 1, lvl = be & 1;
    int d0 = blockIdx.y * 32, hw0 = blockIdx.x * 32;
    const float* gam = lvl ? gi : gv;
    const float* bet = lvl ? bei : bev;
    const float* ip = conv + (size_t)be * DD * HWW;
    #pragma unroll
    for (int j = 0; j < 4; j++) {
        int d = d0 + threadIdx.y + j * 8;
        float mean = stats[(be*32 + (d >> 4)) * 2];
        float rstd = stats[(be*32 + (d >> 4)) * 2 + 1];
        float v = ip[(size_t)d * HWW + hw0 + threadIdx.x];
        tile[threadIdx.y + j*8][threadIdx.x] = (v - mean) * rstd * gam[d] + bet[d];
    }
    __syncthreads();
    #pragma unroll
    for (int j = 0; j < 4; j++) {
        int hw = hw0 + threadIdx.y + j * 8;
        int d  = d0 + threadIdx.x;
        float v = tile[threadIdx.x][threadIdx.y + j*8];
        size_t o = ((size_t)b * LQQ + (size_t)lvl * HWW + hw) * DD + d;
        src[o]   = v;
        query[o] = v + le[lvl * DD + d];
    }
}

// ---------------- softmax over last-8 per (b,q,head) ----------------
__global__ void softmax8(float* __restrict__ aw, int total)
{
    int i = blockIdx.x * blockDim.x + threadIdx.x;
    if (i >= total) return;
    float* p = aw + (size_t)i * 8;
    float4 p0 = *(float4*)(p);
    float4 p1 = *(float4*)(p + 4);
    float m = fmaxf(fmaxf(fmaxf(p0.x, p0.y), fmaxf(p0.z, p0.w)),
                    fmaxf(fmaxf(p1.x, p1.y), fmaxf(p1.z, p1.w)));
    float e0 = expf(p0.x - m), e1 = expf(p0.y - m), e2 = expf(p0.z - m), e3 = expf(p0.w - m);
    float e4 = expf(p1.x - m), e5 = expf(p1.y - m), e6 = expf(p1.z - m), e7 = expf(p1.w - m);
    float inv = 1.f / (e0 + e1 + e2 + e3 + e4 + e5 + e6 + e7);
    p0.x = e0*inv; p0.y = e1*inv; p0.z = e2*inv; p0.w = e3*inv;
    p1.x = e4*inv; p1.y = e5*inv; p1.z = e6*inv; p1.w = e7*inv;
    *(float4*)(p)     = p0;
    *(float4*)(p + 4) = p1;
}

// ---------------- deformable sampling: one block per (b,q), 512 threads ----------------
__global__ __launch_bounds__(512) void msda_sample(
    const float* __restrict__ vproj, const float* __restrict__ off,
    const float* __restrict__ aw, float* __restrict__ msout)
{
    int bq = blockIdx.x;
    int b = bq >> 11;
    int q = bq & 2047;
    int hw = q & 1023;
    float refx = ((hw & 31) + 0.5f) * (1.f / 32.f);
    float refy = ((hw >> 5) + 0.5f) * (1.f / 32.f);
    __shared__ float sx[64], sy[64], sw[64];
    int t = threadIdx.x;
    if (t < 64) {
        // t = head*8 + (l*4+p); off flat layout is exactly t*2 (+c)
        const float* op = off + ((size_t)bq * 64 + t) * 2;
        float lx = refx + op[0] * (1.f / 32.f);
        float ly = refy + op[1] * (1.f / 32.f);
        sx[t] = lx * 32.f - 0.5f;
        sy[t] = ly * 32.f - 0.5f;
        sw[t] = aw[(size_t)bq * 64 + t];
    }
    __syncthreads();
    int head = t >> 6, dh = t & 63;
    const float* vb = vproj + (size_t)b * LQQ * DD + head * 64 + dh;
    float acc = 0.f;
    #pragma unroll
    for (int lp = 0; lp < 8; lp++) {
        int l = lp >> 2;
        float xs = sx[head*8 + lp], ys = sy[head*8 + lp], w = sw[head*8 + lp];
        float x0f = floorf(xs), y0f = floorf(ys);
        float fx = xs - x0f, fy = ys - y0f;
        int x0 = (int)x0f, y0 = (int)y0f;
        int x1 = x0 + 1, y1 = y0 + 1;
        const float* vl = vb + (size_t)l * HWW * DD;
        bool xa = (unsigned)x0 < 32u, xb = (unsigned)x1 < 32u;
        bool ya = (unsigned)y0 < 32u, yb = (unsigned)y1 < 32u;
        float v00 = (ya && xa) ? vl[(size_t)(y0*32 + x0) * DD] : 0.f;
        float v01 = (ya && xb) ? vl[(size_t)(y0*32 + x1) * DD] : 0.f;
        float v10 = (yb && xa) ? vl[(size_t)(y1*32 + x0) * DD] : 0.f;
        float v11 = (yb && xb) ? vl[(size_t)(y1*32 + x1) * DD] : 0.f;
        float s = v00 * (1.f-fy) * (1.f-fx) + v01 * (1.f-fy) * fx
                + v10 * fy * (1.f-fx)       + v11 * fy * fx;
        acc = fmaf(w, s, acc);
    }
    msout[(size_t)bq * DD + t] = acc;
}

// ---------------- residual + LayerNorm (one block per row) ----------------
__global__ void ln_res(const float* __restrict__ src, const float* __restrict__ att,
                       const float* __restrict__ g, const float* __restrict__ be,
                       float* __restrict__ out)
{
    int row = blockIdx.x;
    size_t base = (size_t)row * DD;
    int t = threadIdx.x; // 256
    float v0 = src[base + t]       + att[base + t];
    float v1 = src[base + t + 256] + att[base + t + 256];
    float s = v0 + v1, sq = v0*v0 + v1*v1;
    __shared__ float red[16];
    for (int o = 16; o > 0; o >>= 1) {
        s  += __shfl_down_sync(0xffffffffu, s,  o);
        sq += __shfl_down_sync(0xffffffffu, sq, o);
    }
    if ((t & 31) == 0) { red[t >> 5] = s; red[8 + (t >> 5)] = sq; }
    __syncthreads();
    if (t < 32) {
        s  = (t < 8) ? red[t]     : 0.f;
        sq = (t < 8) ? red[8 + t] : 0.f;
        for (int o = 4; o > 0; o >>= 1) {
            s  += __shfl_down_sync(0xffffffffu, s,  o);
            sq += __shfl_down_sync(0xffffffffu, sq, o);
        }
        if (t == 0) { red[0] = s; red[8] = sq; }
    }
    __syncthreads();
    float mu   = red[0] * (1.f / 512.f);
    float var  = red[8] * (1.f / 512.f) - mu * mu;
    float rstd = rsqrtf(var + 1e-5f);
    out[base + t]       = (v0 - mu) * rstd * g[t]       + be[t];
    out[base + t + 256] = (v1 - mu) * rstd * g[t + 256] + be[t + 256];
}

// ---------------- final GN normalize -> output ----------------
__global__ void gn2_finish(const float* __restrict__ x, const float* __restrict__ stats,
    const float* __restrict__ gc, const float* __restrict__ bec, float* __restrict__ out)
{
    size_t i = (size_t)blockIdx.x * blockDim.x + threadIdx.x;
    // total = B*768*1024 = 6291456, grid sized exactly
    int hwch = (int)(i >> 10);
    int ch = hwch % 768;
    int b  = hwch / 768;
    int g  = ch / 24;
    float mean = stats[(b*32 + g) * 2];
    float rstd = stats[(b*32 + g) * 2 + 1];
    out[i] = (x[i] - mean) * rstd * gc[ch] + bec[ch];
}

// ---------------- launcher ----------------
extern "C" void kernel_launch(void* const* d_in, const int* in_sizes, int n_in,
                              void* d_out, int out_size)
{
    const float* input_v = (const float*)d_in[0];
    const float* input_i = (const float*)d_in[1];
    const float* wv      = (const float*)d_in[2];
    const float* bv      = (const float*)d_in[3];
    const float* gv      = (const float*)d_in[4];
    const float* bev     = (const float*)d_in[5];
    const float* wi      = (const float*)d_in[6];
    const float* bi      = (const float*)d_in[7];
    const float* gi      = (const float*)d_in[8];
    const float* bei     = (const float*)d_in[9];
    const float* le      = (const float*)d_in[10];
    const float* w_off   = (const float*)d_in[11];
    const float* b_off   = (const float*)d_in[12];
    const float* w_attn  = (const float*)d_in[13];
    const float* b_attn  = (const float*)d_in[14];
    const float* w_val   = (const float*)d_in[15];
    const float* b_val   = (const float*)d_in[16];
    const float* w_out   = (const float*)d_in[17];
    const float* b_out   = (const float*)d_in[18];
    const float* ln_g    = (const float*)d_in[19];
    const float* ln_b    = (const float*)d_in[20];
    const float* wc      = (const float*)d_in[21];
    const float* bc      = (const float*)d_in[22];
    const float* gc      = (const float*)d_in[23];
    const float* bec     = (const float*)d_in[24];

    float *conv1, *src, *query, *vproj, *offb, *awb, *msout, *attno, *lnout, *conv2, *st1, *st2;
    cudaGetSymbolAddress((void**)&conv1, g_conv1);
    cudaGetSymbolAddress((void**)&src,   g_src);
    cudaGetSymbolAddress((void**)&query, g_query);
    cudaGetSymbolAddress((void**)&vproj, g_vproj);
    cudaGetSymbolAddress((void**)&offb,  g_off);
    cudaGetSymbolAddress((void**)&awb,   g_aw);
    cudaGetSymbolAddress((void**)&msout, g_msout);
    cudaGetSymbolAddress((void**)&attno, g_attno);
    cudaGetSymbolAddress((void**)&lnout, g_lnout);
    cudaGetSymbolAddress((void**)&conv2, g_conv2);
    cudaGetSymbolAddress((void**)&st1,   g_stats1);
    cudaGetSymbolAddress((void**)&st2,   g_stats2);

    // 1) conv1x1 for v and i  (M=512, N=1024, K=768, batched over B)
    sgemm_nn<<<dim3(8, 4, BB), 256>>>(wv, input_v, conv1,            bv, DD, HWW, CC,
                                      (long)CC*HWW, (long)2*DD*HWW);
    sgemm_nn<<<dim3(8, 4, BB), 256>>>(wi, input_i, conv1 + (size_t)DD*HWW, bi, DD, HWW, CC,
                                      (long)CC*HWW, (long)2*DD*HWW);
    // 2) GN stats + normalize/transpose -> src, query
    gn_stats<<<dim3(32, BB*2), 256>>>(conv1, st1, 16 * HWW);
    gn1_finish<<<dim3(32, 16, BB*2), dim3(32, 8)>>>(conv1, st1, gv, bev, gi, bei, le, src, query);
    // 3) projections
    sgemm_nt<<<dim3(4, 128), 256>>>(src,   w_val,  vproj, b_val,  BB*LQQ, DD,  DD);
    sgemm_nt<<<dim3(1, 128), 256>>>(query, w_off,  offb,  b_off,  BB*LQQ, 128, DD);
    sgemm_nt<<<dim3(1, 128), 256>>>(query, w_attn, awb,   b_attn, BB*LQQ, 64,  DD);
    // 4) softmax over (LEVELS*POINTS)
    softmax8<<<512, 256>>>(awb, BB*LQQ*NHEAD);
    // 5) deformable sampling + weighted sum
    msda_sample<<<BB*LQQ, 512>>>(vproj, offb, awb, msout);
    // 6) output projection
    sgemm_nt<<<dim3(4, 128), 256>>>(msout, w_out, attno, b_out, BB*LQQ, DD, DD);
    // 7) residual + LayerNorm
    ln_res<<<BB*LQQ, 256>>>(src, attno, ln_g, ln_b, lnout);
    // 8) final conv1x1 (M=768, N=1024, K=1024, batched)
    sgemm_conv2<<<dim3(8, 6, BB), 256>>>(wc, lnout, conv2, bc);
    // 9) final GN
    gn_stats<<<dim3(32, BB), 256>>>(conv2, st2, 24 * HWW);
    gn2_finish<<<24576, 256>>>(conv2, st2, gc, bec, (float*)d_out);
}